// round 4
// baseline (speedup 1.0000x reference)
#include <cuda_runtime.h>

#define N_NODES 50000
#define N_EDGES 600000
#define D 128
#define M_PAD 50048  // 391 * 128

// Scratch (allowed: __device__ globals, no runtime allocation).
// Pad rows [50000, 50048) of g_agg are never written -> stay BSS-zero forever,
// so GEMM1 reading them is deterministic.
__device__ float g_agg[(size_t)M_PAD * D];
__device__ float g_h[(size_t)M_PAD * D];
__device__ int g_is64;  // 1 if edge_index buffer is int64, 0 if int32

// Detect edge_index dtype: int64 little-endian => high 32-bit word of every
// index is 0 (indices < 2^31). 4096 consecutive zero odd-words cannot happen
// with genuine random int32 indices.
__global__ void probe_kernel(const int* __restrict__ ei) {
    __shared__ int nonzero;
    if (threadIdx.x == 0) nonzero = 0;
    __syncthreads();
    for (int i = threadIdx.x; i < 4096; i += blockDim.x) {
        if (ei[2 * i + 1] != 0) nonzero = 1;  // benign race, any write works
    }
    __syncthreads();
    if (threadIdx.x == 0) g_is64 = (nonzero == 0) ? 1 : 0;
}

// g_agg[i] = (1 + eps) * x[i]   (also resets the accumulator every graph replay)
__global__ void init_kernel(const float4* __restrict__ x,
                            const float* __restrict__ eps) {
    int i = blockIdx.x * blockDim.x + threadIdx.x;
    const int n4 = N_NODES * (D / 4);
    if (i < n4) {
        float s = 1.0f + __ldg(eps);
        float4 v = x[i];
        v.x *= s; v.y *= s; v.z *= s; v.w *= s;
        ((float4*)g_agg)[i] = v;
    }
}

// One warp per edge: lane l handles floats [4l, 4l+4) of the 128-wide row.
__global__ void scatter_kernel(const float4* __restrict__ x,
                               const int* __restrict__ ei) {
    long long idx = (long long)blockIdx.x * blockDim.x + threadIdx.x;
    int e = (int)(idx >> 5);
    int lane = (int)(idx & 31);
    if (e >= N_EDGES) return;
    int src, dst;
    if (g_is64) {
        // int64 little-endian: take low words at stride 2
        src = ei[2 * e];
        dst = ei[2 * (N_EDGES + e)];
    } else {
        src = ei[e];             // edge_index[0][e]
        dst = ei[N_EDGES + e];   // edge_index[1][e]
    }
    // Bounds guard: any remaining surprise becomes rel_err, not a crash.
    if ((unsigned)src >= (unsigned)N_NODES || (unsigned)dst >= (unsigned)N_NODES)
        return;
    float4 v = x[(long long)src * 32 + lane];
    float* a = g_agg + (long long)dst * D + lane * 4;
    atomicAdd(a + 0, v.x);
    atomicAdd(a + 1, v.y);
    atomicAdd(a + 2, v.z);
    atomicAdd(a + 3, v.w);
}

// out[m, n] = relu(sum_k A[m,k] * W[k,n] + bias[n])
// Block tile 128x128, K=128, BK=16, 256 threads, 8x8 per-thread register tile.
// A is padded to M_PAD rows so loads need no guard; stores guarded by M_store.
__global__ void __launch_bounds__(256) gemm_relu_kernel(
    const float* __restrict__ A, const float* __restrict__ W,
    const float* __restrict__ bias, float* __restrict__ out, int M_store) {
    __shared__ float As[16][128];  // As[k][m]
    __shared__ float Bs[16][132];  // Bs[k][n], padded to dodge conflicts

    const int t = threadIdx.x;
    const int m0 = blockIdx.x * 128;
    const int tm = (t / 16) * 8;
    const int tn = (t % 16) * 8;

    float acc[8][8];
#pragma unroll
    for (int i = 0; i < 8; i++)
#pragma unroll
        for (int j = 0; j < 8; j++) acc[i][j] = 0.0f;

    for (int kc = 0; kc < 128; kc += 16) {
        // Load A tile: 128 rows x 16 k = 512 float4, 2 per thread (transposed store)
#pragma unroll
        for (int l = 0; l < 2; l++) {
            int j = t + l * 256;       // 0..511
            int r = j >> 2;            // row in tile 0..127
            int k4 = (j & 3) * 4;      // 0,4,8,12
            float4 v = *(const float4*)(A + (long long)(m0 + r) * D + kc + k4);
            As[k4 + 0][r] = v.x;
            As[k4 + 1][r] = v.y;
            As[k4 + 2][r] = v.z;
            As[k4 + 3][r] = v.w;
        }
        // Load W tile: 16 k-rows x 128 cols = 512 float4, 2 per thread
#pragma unroll
        for (int l = 0; l < 2; l++) {
            int j = t + l * 256;
            int kk = j >> 5;           // 0..15
            int c4 = (j & 31) * 4;     // 0..124
            float4 v = *(const float4*)(W + (kc + kk) * D + c4);
            Bs[kk][c4 + 0] = v.x;
            Bs[kk][c4 + 1] = v.y;
            Bs[kk][c4 + 2] = v.z;
            Bs[kk][c4 + 3] = v.w;
        }
        __syncthreads();

#pragma unroll
        for (int k = 0; k < 16; k++) {
            float a[8], b[8];
#pragma unroll
            for (int i = 0; i < 8; i++) a[i] = As[k][tm + i];
#pragma unroll
            for (int j = 0; j < 8; j++) b[j] = Bs[k][tn + j];
#pragma unroll
            for (int i = 0; i < 8; i++)
#pragma unroll
                for (int j = 0; j < 8; j++) acc[i][j] += a[i] * b[j];
        }
        __syncthreads();
    }

    float bv[8];
#pragma unroll
    for (int j = 0; j < 8; j++) bv[j] = __ldg(bias + tn + j);

#pragma unroll
    for (int i = 0; i < 8; i++) {
        int row = m0 + tm + i;
        if (row < M_store) {
            float* o = out + (long long)row * D + tn;
#pragma unroll
            for (int j = 0; j < 8; j += 4) {
                float4 v;
                v.x = fmaxf(acc[i][j + 0] + bv[j + 0], 0.0f);
                v.y = fmaxf(acc[i][j + 1] + bv[j + 1], 0.0f);
                v.z = fmaxf(acc[i][j + 2] + bv[j + 2], 0.0f);
                v.w = fmaxf(acc[i][j + 3] + bv[j + 3], 0.0f);
                *(float4*)(o + j) = v;
            }
        }
    }
}

extern "C" void kernel_launch(void* const* d_in, const int* in_sizes, int n_in,
                              void* d_out, int out_size) {
    const float* x = (const float*)d_in[0];
    const int* ei = (const int*)d_in[1];
    const float* W1 = (const float*)d_in[2];
    const float* b1 = (const float*)d_in[3];
    const float* W2 = (const float*)d_in[4];
    const float* b2 = (const float*)d_in[5];
    const float* eps = (const float*)d_in[6];
    float* out = (float*)d_out;

    static float* agg = nullptr;
    static float* h = nullptr;
    if (!agg) {
        cudaGetSymbolAddress((void**)&agg, g_agg);
        cudaGetSymbolAddress((void**)&h, g_h);
    }

    // 0) detect edge_index dtype (int32 vs int64)
    probe_kernel<<<1, 256>>>(ei);

    // 1) agg = (1 + eps) * x   (resets accumulator each replay)
    {
        int n4 = N_NODES * (D / 4);
        int threads = 256;
        int blocks = (n4 + threads - 1) / threads;
        init_kernel<<<blocks, threads>>>((const float4*)x, eps);
    }
    // 2) agg[dst] += x[src] for all edges
    {
        long long total = (long long)N_EDGES * 32;
        int threads = 256;
        int blocks = (int)((total + threads - 1) / threads);
        scatter_kernel<<<blocks, threads>>>((const float4*)x, ei);
    }
    // 3) h = relu(agg @ W1 + b1)   (store all padded rows; pad input deterministic)
    {
        int blocks = M_PAD / 128;  // 391
        gemm_relu_kernel<<<blocks, 256>>>(agg, W1, b1, h, M_PAD);
    }
    // 4) out = relu(h @ W2 + b2)   (store guarded to N_NODES)
    {
        int blocks = M_PAD / 128;
        gemm_relu_kernel<<<blocks, 256>>>(h, W2, b2, out, N_NODES);
    }
}

// round 5
// speedup vs baseline: 1.5075x; 1.5075x over previous
#include <cuda_runtime.h>

#define N_NODES 50000
#define N_EDGES 600000
#define D 128
#define M_PAD 50048  // 391 * 128

// Scratch (allowed: __device__ globals, no runtime allocation).
// Pad rows [50000, 50048) of g_agg are never written -> stay BSS-zero forever,
// so GEMM1 reading them is deterministic.
__device__ float g_agg[(size_t)M_PAD * D];
__device__ float g_h[(size_t)M_PAD * D];
__device__ int g_is64;  // 1 if edge_index buffer is int64, 0 if int32

// Detect edge_index dtype: int64 little-endian => high 32-bit word of every
// index is 0 (indices < 2^31). 4096 consecutive zero odd-words cannot happen
// with genuine random int32 indices.
__global__ void probe_kernel(const int* __restrict__ ei) {
    __shared__ int nonzero;
    if (threadIdx.x == 0) nonzero = 0;
    __syncthreads();
    for (int i = threadIdx.x; i < 4096; i += blockDim.x) {
        if (ei[2 * i + 1] != 0) nonzero = 1;  // benign race, any write works
    }
    __syncthreads();
    if (threadIdx.x == 0) g_is64 = (nonzero == 0) ? 1 : 0;
}

// g_agg[i] = (1 + eps) * x[i]   (also resets the accumulator every graph replay)
__global__ void init_kernel(const float4* __restrict__ x,
                            const float* __restrict__ eps) {
    int i = blockIdx.x * blockDim.x + threadIdx.x;
    const int n4 = N_NODES * (D / 4);
    if (i < n4) {
        float s = 1.0f + __ldg(eps);
        float4 v = x[i];
        v.x *= s; v.y *= s; v.z *= s; v.w *= s;
        ((float4*)g_agg)[i] = v;
    }
}

// One warp per edge: lane l handles floats [4l, 4l+4) of the 128-wide row.
// Vector reduction: one 16B red.global.add.v4.f32 per lane instead of four
// scalar atomics -> 4x fewer L2 atomic ops (the scatter was op-count bound).
__global__ void scatter_kernel(const float4* __restrict__ x,
                               const int* __restrict__ ei) {
    long long idx = (long long)blockIdx.x * blockDim.x + threadIdx.x;
    int e = (int)(idx >> 5);
    int lane = (int)(idx & 31);
    if (e >= N_EDGES) return;
    int src, dst;
    if (g_is64) {
        src = ei[2 * e];
        dst = ei[2 * (N_EDGES + e)];
    } else {
        src = ei[e];             // edge_index[0][e]
        dst = ei[N_EDGES + e];   // edge_index[1][e]
    }
    if ((unsigned)src >= (unsigned)N_NODES || (unsigned)dst >= (unsigned)N_NODES)
        return;
    float4 v = x[(long long)src * 32 + lane];
    float* a = g_agg + (long long)dst * D + lane * 4;
    asm volatile("red.global.add.v4.f32 [%0], {%1, %2, %3, %4};"
                 :: "l"(a), "f"(v.x), "f"(v.y), "f"(v.z), "f"(v.w)
                 : "memory");
}

// out[m, n] = relu(sum_k A[m,k] * W[k,n] + bias[n])
// Block tile 128x128, K=128, BK=16, 256 threads, 8x8 per-thread register tile.
// A is padded to M_PAD rows so loads need no guard; stores guarded by M_store.
__global__ void __launch_bounds__(256) gemm_relu_kernel(
    const float* __restrict__ A, const float* __restrict__ W,
    const float* __restrict__ bias, float* __restrict__ out, int M_store) {
    __shared__ float As[16][128];  // As[k][m]
    __shared__ float Bs[16][132];  // Bs[k][n], padded to dodge conflicts

    const int t = threadIdx.x;
    const int m0 = blockIdx.x * 128;
    const int tm = (t / 16) * 8;
    const int tn = (t % 16) * 8;

    float acc[8][8];
#pragma unroll
    for (int i = 0; i < 8; i++)
#pragma unroll
        for (int j = 0; j < 8; j++) acc[i][j] = 0.0f;

    for (int kc = 0; kc < 128; kc += 16) {
        // Load A tile: 128 rows x 16 k = 512 float4, 2 per thread (transposed store)
#pragma unroll
        for (int l = 0; l < 2; l++) {
            int j = t + l * 256;       // 0..511
            int r = j >> 2;            // row in tile 0..127
            int k4 = (j & 3) * 4;      // 0,4,8,12
            float4 v = *(const float4*)(A + (long long)(m0 + r) * D + kc + k4);
            As[k4 + 0][r] = v.x;
            As[k4 + 1][r] = v.y;
            As[k4 + 2][r] = v.z;
            As[k4 + 3][r] = v.w;
        }
        // Load W tile: 16 k-rows x 128 cols = 512 float4, 2 per thread
#pragma unroll
        for (int l = 0; l < 2; l++) {
            int j = t + l * 256;
            int kk = j >> 5;           // 0..15
            int c4 = (j & 31) * 4;     // 0..124
            float4 v = *(const float4*)(W + (kc + kk) * D + c4);
            Bs[kk][c4 + 0] = v.x;
            Bs[kk][c4 + 1] = v.y;
            Bs[kk][c4 + 2] = v.z;
            Bs[kk][c4 + 3] = v.w;
        }
        __syncthreads();

#pragma unroll
        for (int k = 0; k < 16; k++) {
            float a[8], b[8];
#pragma unroll
            for (int i = 0; i < 8; i++) a[i] = As[k][tm + i];
#pragma unroll
            for (int j = 0; j < 8; j++) b[j] = Bs[k][tn + j];
#pragma unroll
            for (int i = 0; i < 8; i++)
#pragma unroll
                for (int j = 0; j < 8; j++) acc[i][j] += a[i] * b[j];
        }
        __syncthreads();
    }

    float bv[8];
#pragma unroll
    for (int j = 0; j < 8; j++) bv[j] = __ldg(bias + tn + j);

#pragma unroll
    for (int i = 0; i < 8; i++) {
        int row = m0 + tm + i;
        if (row < M_store) {
            float* o = out + (long long)row * D + tn;
#pragma unroll
            for (int j = 0; j < 8; j += 4) {
                float4 v;
                v.x = fmaxf(acc[i][j + 0] + bv[j + 0], 0.0f);
                v.y = fmaxf(acc[i][j + 1] + bv[j + 1], 0.0f);
                v.z = fmaxf(acc[i][j + 2] + bv[j + 2], 0.0f);
                v.w = fmaxf(acc[i][j + 3] + bv[j + 3], 0.0f);
                *(float4*)(o + j) = v;
            }
        }
    }
}

extern "C" void kernel_launch(void* const* d_in, const int* in_sizes, int n_in,
                              void* d_out, int out_size) {
    const float* x = (const float*)d_in[0];
    const int* ei = (const int*)d_in[1];
    const float* W1 = (const float*)d_in[2];
    const float* b1 = (const float*)d_in[3];
    const float* W2 = (const float*)d_in[4];
    const float* b2 = (const float*)d_in[5];
    const float* eps = (const float*)d_in[6];
    float* out = (float*)d_out;

    static float* agg = nullptr;
    static float* h = nullptr;
    if (!agg) {
        cudaGetSymbolAddress((void**)&agg, g_agg);
        cudaGetSymbolAddress((void**)&h, g_h);
    }

    // 0) detect edge_index dtype (int32 vs int64)
    probe_kernel<<<1, 256>>>(ei);

    // 1) agg = (1 + eps) * x   (resets accumulator each replay)
    {
        int n4 = N_NODES * (D / 4);
        int threads = 256;
        int blocks = (n4 + threads - 1) / threads;
        init_kernel<<<blocks, threads>>>((const float4*)x, eps);
    }
    // 2) agg[dst] += x[src] for all edges
    {
        long long total = (long long)N_EDGES * 32;
        int threads = 256;
        int blocks = (int)((total + threads - 1) / threads);
        scatter_kernel<<<blocks, threads>>>((const float4*)x, ei);
    }
    // 3) h = relu(agg @ W1 + b1)   (store all padded rows; pad input deterministic)
    {
        int blocks = M_PAD / 128;  // 391
        gemm_relu_kernel<<<blocks, 256>>>(agg, W1, b1, h, M_PAD);
    }
    // 4) out = relu(h @ W2 + b2)   (store guarded to N_NODES)
    {
        int blocks = M_PAD / 128;
        gemm_relu_kernel<<<blocks, 256>>>(h, W2, b2, out, N_NODES);
    }
}